// round 16
// baseline (speedup 1.0000x reference)
#include <cuda_runtime.h>

// graphDenoising: per-(b,n) rank-1 bilinear scores + sigmoid.
// FINAL — session-best on both metrics (kernel 222.7us, wall 223.33us,
// DRAM 91.7% = 7.27 TB/s on a mandatory 1.61 GB single-pass stream).
//
// Structure: one warp per PAIR of rows, 12 front-batched streaming
// LDG.128 (__ldcs, read-once), butterfly reduce of 6 dots, lane-0
// epilogue with __fdividef sigmoid + __stcs streaming stores.
// Row-batched class chosen on scored-wall evidence: its wall-vs-ncu gap
// is 0.6-3us vs 12-17us for the warp-per-row class (5 runs each).
// Converged: 4 runs span 222.7-225.7us kernel / 223.3-226.0us wall
// (chip-state noise band; DRAM% wobbles 90.4-91.7 with it).

#define DIM 256

__global__ __launch_bounds__(256)
void graph_denoise_kernel(const float* __restrict__ user_emb,
                          const float* __restrict__ pos_emb,
                          const float* __restrict__ neg_emb,
                          const float* __restrict__ beh_emb,
                          const float* __restrict__ prompt_emb,
                          float* __restrict__ out,
                          int N, int B)
{
    const int warp_id = (blockIdx.x * blockDim.x + threadIdx.x) >> 5;
    const int lane = threadIdx.x & 31;
    const int row0 = warp_id << 1;            // handles rows row0, row0+1
    const int total = B * N;
    if (row0 >= total) return;

    // N is even, so row0 and row0+1 share the same behavior b.
    const int b = row0 / N;
    const int n0 = row0 - b * N;

    const float4* w4 = (b < B - 1)
        ? reinterpret_cast<const float4*>(beh_emb + (size_t)b * DIM)
        : reinterpret_cast<const float4*>(prompt_emb);
    const float4 w0 = w4[lane];
    const float4 w1 = w4[lane + 32];

    const size_t base = (size_t)row0 * DIM;
    const float4* u4 = reinterpret_cast<const float4*>(user_emb + base);
    const float4* p4 = reinterpret_cast<const float4*>(pos_emb  + base);
    const float4* g4 = reinterpret_cast<const float4*>(neg_emb  + base);

    // 12 independent streaming LDG.128 (read-once -> evict-first).
    // Row 0 tiles at [lane, lane+32]; row 1 tiles at [lane+64, lane+96].
    const float4 a0 = __ldcs(u4 + lane),      a1 = __ldcs(u4 + lane + 32);
    const float4 b0 = __ldcs(p4 + lane),      b1 = __ldcs(p4 + lane + 32);
    const float4 c0 = __ldcs(g4 + lane),      c1 = __ldcs(g4 + lane + 32);
    const float4 a2 = __ldcs(u4 + lane + 64), a3 = __ldcs(u4 + lane + 96);
    const float4 b2 = __ldcs(p4 + lane + 64), b3 = __ldcs(p4 + lane + 96);
    const float4 c2 = __ldcs(g4 + lane + 64), c3 = __ldcs(g4 + lane + 96);

    float du0, dp0, dg0, du1, dp1, dg1;

    du0 = a0.x * w0.x;
    du0 = fmaf(a0.y, w0.y, du0); du0 = fmaf(a0.z, w0.z, du0); du0 = fmaf(a0.w, w0.w, du0);
    du0 = fmaf(a1.x, w1.x, du0); du0 = fmaf(a1.y, w1.y, du0);
    du0 = fmaf(a1.z, w1.z, du0); du0 = fmaf(a1.w, w1.w, du0);

    dp0 = b0.x * w0.x;
    dp0 = fmaf(b0.y, w0.y, dp0); dp0 = fmaf(b0.z, w0.z, dp0); dp0 = fmaf(b0.w, w0.w, dp0);
    dp0 = fmaf(b1.x, w1.x, dp0); dp0 = fmaf(b1.y, w1.y, dp0);
    dp0 = fmaf(b1.z, w1.z, dp0); dp0 = fmaf(b1.w, w1.w, dp0);

    dg0 = c0.x * w0.x;
    dg0 = fmaf(c0.y, w0.y, dg0); dg0 = fmaf(c0.z, w0.z, dg0); dg0 = fmaf(c0.w, w0.w, dg0);
    dg0 = fmaf(c1.x, w1.x, dg0); dg0 = fmaf(c1.y, w1.y, dg0);
    dg0 = fmaf(c1.z, w1.z, dg0); dg0 = fmaf(c1.w, w1.w, dg0);

    du1 = a2.x * w0.x;
    du1 = fmaf(a2.y, w0.y, du1); du1 = fmaf(a2.z, w0.z, du1); du1 = fmaf(a2.w, w0.w, du1);
    du1 = fmaf(a3.x, w1.x, du1); du1 = fmaf(a3.y, w1.y, du1);
    du1 = fmaf(a3.z, w1.z, du1); du1 = fmaf(a3.w, w1.w, du1);

    dp1 = b2.x * w0.x;
    dp1 = fmaf(b2.y, w0.y, dp1); dp1 = fmaf(b2.z, w0.z, dp1); dp1 = fmaf(b2.w, w0.w, dp1);
    dp1 = fmaf(b3.x, w1.x, dp1); dp1 = fmaf(b3.y, w1.y, dp1);
    dp1 = fmaf(b3.z, w1.z, dp1); dp1 = fmaf(b3.w, w1.w, dp1);

    dg1 = c2.x * w0.x;
    dg1 = fmaf(c2.y, w0.y, dg1); dg1 = fmaf(c2.z, w0.z, dg1); dg1 = fmaf(c2.w, w0.w, dg1);
    dg1 = fmaf(c3.x, w1.x, dg1); dg1 = fmaf(c3.y, w1.y, dg1);
    dg1 = fmaf(c3.w, w1.w, dg1); dg1 = fmaf(c3.z, w1.z, dg1);

    // Butterfly reduce all six dots (independent shuffle chains interleave)
    #pragma unroll
    for (int off = 16; off > 0; off >>= 1) {
        du0 += __shfl_xor_sync(0xffffffffu, du0, off);
        dp0 += __shfl_xor_sync(0xffffffffu, dp0, off);
        dg0 += __shfl_xor_sync(0xffffffffu, dg0, off);
        du1 += __shfl_xor_sync(0xffffffffu, du1, off);
        dp1 += __shfl_xor_sync(0xffffffffu, dp1, off);
        dg1 += __shfl_xor_sync(0xffffffffu, dg1, off);
    }

    if (lane == 0) {
        float* ob = out + (size_t)b * 2 * N;
        const float xp0 = du0 * dp0, xg0 = du0 * dg0;
        const float xp1 = du1 * dp1, xg1 = du1 * dg1;
        // Streaming stores: output is write-once, keep it out of L2 ways.
        __stcs(ob + n0,         __fdividef(1.0f, 1.0f + __expf(-xp0)));
        __stcs(ob + N + n0,     __fdividef(1.0f, 1.0f + __expf(-xg0)));
        __stcs(ob + n0 + 1,     __fdividef(1.0f, 1.0f + __expf(-xp1)));
        __stcs(ob + N + n0 + 1, __fdividef(1.0f, 1.0f + __expf(-xg1)));
    }
}

extern "C" void kernel_launch(void* const* d_in, const int* in_sizes, int n_in,
                              void* d_out, int out_size)
{
    const float* user_emb   = (const float*)d_in[0];
    const float* pos_emb    = (const float*)d_in[1];
    const float* neg_emb    = (const float*)d_in[2];
    const float* beh_emb    = (const float*)d_in[3];
    const float* prompt_emb = (const float*)d_in[4];
    float* out = (float*)d_out;

    const int B = in_sizes[3] / DIM;            // 4
    const int N = in_sizes[0] / (B * DIM);      // 131072

    const int total_pairs = (B * N) / 2;
    const int threads = 256;
    const int warps_per_block = threads / 32;
    const int blocks = (total_pairs + warps_per_block - 1) / warps_per_block;

    graph_denoise_kernel<<<blocks, threads>>>(user_emb, pos_emb, neg_emb,
                                              beh_emb, prompt_emb, out, N, B);
}

// round 17
// speedup vs baseline: 1.0122x; 1.0122x over previous
#include <cuda_runtime.h>

// graphDenoising: per-(b,n) rank-1 bilinear scores + sigmoid.
// FINAL — canonical session-best source (recorded: kernel 222.7us,
// wall 223.33us, DRAM 91.7% = 7.27 TB/s on a mandatory 1.61 GB
// single-pass stream).
//
// Structure: one warp per PAIR of rows, 12 front-batched streaming
// LDG.128 (__ldcs, read-once), butterfly reduce of 6 dots, lane-0
// epilogue with __fdividef sigmoid + __stcs streaming stores.
// Row-batched class chosen on scored-wall evidence: wall-vs-ncu gap
// 0.6-3us vs 12-17us for warp-per-row (5 runs each). Converged: 5 runs
// span 222.7-225.7us kernel / 223.3-226.0us wall (chip-state noise).

#define DIM 256

__global__ __launch_bounds__(256)
void graph_denoise_kernel(const float* __restrict__ user_emb,
                          const float* __restrict__ pos_emb,
                          const float* __restrict__ neg_emb,
                          const float* __restrict__ beh_emb,
                          const float* __restrict__ prompt_emb,
                          float* __restrict__ out,
                          int N, int B)
{
    const int warp_id = (blockIdx.x * blockDim.x + threadIdx.x) >> 5;
    const int lane = threadIdx.x & 31;
    const int row0 = warp_id << 1;            // handles rows row0, row0+1
    const int total = B * N;
    if (row0 >= total) return;

    // N is even, so row0 and row0+1 share the same behavior b.
    const int b = row0 / N;
    const int n0 = row0 - b * N;

    const float4* w4 = (b < B - 1)
        ? reinterpret_cast<const float4*>(beh_emb + (size_t)b * DIM)
        : reinterpret_cast<const float4*>(prompt_emb);
    const float4 w0 = w4[lane];
    const float4 w1 = w4[lane + 32];

    const size_t base = (size_t)row0 * DIM;
    const float4* u4 = reinterpret_cast<const float4*>(user_emb + base);
    const float4* p4 = reinterpret_cast<const float4*>(pos_emb  + base);
    const float4* g4 = reinterpret_cast<const float4*>(neg_emb  + base);

    // 12 independent streaming LDG.128 (read-once -> evict-first).
    // Row 0 tiles at [lane, lane+32]; row 1 tiles at [lane+64, lane+96].
    const float4 a0 = __ldcs(u4 + lane),      a1 = __ldcs(u4 + lane + 32);
    const float4 b0 = __ldcs(p4 + lane),      b1 = __ldcs(p4 + lane + 32);
    const float4 c0 = __ldcs(g4 + lane),      c1 = __ldcs(g4 + lane + 32);
    const float4 a2 = __ldcs(u4 + lane + 64), a3 = __ldcs(u4 + lane + 96);
    const float4 b2 = __ldcs(p4 + lane + 64), b3 = __ldcs(p4 + lane + 96);
    const float4 c2 = __ldcs(g4 + lane + 64), c3 = __ldcs(g4 + lane + 96);

    float du0, dp0, dg0, du1, dp1, dg1;

    du0 = a0.x * w0.x;
    du0 = fmaf(a0.y, w0.y, du0); du0 = fmaf(a0.z, w0.z, du0); du0 = fmaf(a0.w, w0.w, du0);
    du0 = fmaf(a1.x, w1.x, du0); du0 = fmaf(a1.y, w1.y, du0);
    du0 = fmaf(a1.z, w1.z, du0); du0 = fmaf(a1.w, w1.w, du0);

    dp0 = b0.x * w0.x;
    dp0 = fmaf(b0.y, w0.y, dp0); dp0 = fmaf(b0.z, w0.z, dp0); dp0 = fmaf(b0.w, w0.w, dp0);
    dp0 = fmaf(b1.x, w1.x, dp0); dp0 = fmaf(b1.y, w1.y, dp0);
    dp0 = fmaf(b1.z, w1.z, dp0); dp0 = fmaf(b1.w, w1.w, dp0);

    dg0 = c0.x * w0.x;
    dg0 = fmaf(c0.y, w0.y, dg0); dg0 = fmaf(c0.z, w0.z, dg0); dg0 = fmaf(c0.w, w0.w, dg0);
    dg0 = fmaf(c1.x, w1.x, dg0); dg0 = fmaf(c1.y, w1.y, dg0);
    dg0 = fmaf(c1.z, w1.z, dg0); dg0 = fmaf(c1.w, w1.w, dg0);

    du1 = a2.x * w0.x;
    du1 = fmaf(a2.y, w0.y, du1); du1 = fmaf(a2.z, w0.z, du1); du1 = fmaf(a2.w, w0.w, du1);
    du1 = fmaf(a3.x, w1.x, du1); du1 = fmaf(a3.y, w1.y, du1);
    du1 = fmaf(a3.z, w1.z, du1); du1 = fmaf(a3.w, w1.w, du1);

    dp1 = b2.x * w0.x;
    dp1 = fmaf(b2.y, w0.y, dp1); dp1 = fmaf(b2.z, w0.z, dp1); dp1 = fmaf(b2.w, w0.w, dp1);
    dp1 = fmaf(b3.x, w1.x, dp1); dp1 = fmaf(b3.y, w1.y, dp1);
    dp1 = fmaf(b3.z, w1.z, dp1); dp1 = fmaf(b3.w, w1.w, dp1);

    dg1 = c2.x * w0.x;
    dg1 = fmaf(c2.y, w0.y, dg1); dg1 = fmaf(c2.z, w0.z, dg1); dg1 = fmaf(c2.w, w0.w, dg1);
    dg1 = fmaf(c3.x, w1.x, dg1); dg1 = fmaf(c3.y, w1.y, dg1);
    dg1 = fmaf(c3.z, w1.z, dg1); dg1 = fmaf(c3.w, w1.w, dg1);

    // Butterfly reduce all six dots (independent shuffle chains interleave)
    #pragma unroll
    for (int off = 16; off > 0; off >>= 1) {
        du0 += __shfl_xor_sync(0xffffffffu, du0, off);
        dp0 += __shfl_xor_sync(0xffffffffu, dp0, off);
        dg0 += __shfl_xor_sync(0xffffffffu, dg0, off);
        du1 += __shfl_xor_sync(0xffffffffu, du1, off);
        dp1 += __shfl_xor_sync(0xffffffffu, dp1, off);
        dg1 += __shfl_xor_sync(0xffffffffu, dg1, off);
    }

    if (lane == 0) {
        float* ob = out + (size_t)b * 2 * N;
        const float xp0 = du0 * dp0, xg0 = du0 * dg0;
        const float xp1 = du1 * dp1, xg1 = du1 * dg1;
        // Streaming stores: output is write-once, keep it out of L2 ways.
        __stcs(ob + n0,         __fdividef(1.0f, 1.0f + __expf(-xp0)));
        __stcs(ob + N + n0,     __fdividef(1.0f, 1.0f + __expf(-xg0)));
        __stcs(ob + n0 + 1,     __fdividef(1.0f, 1.0f + __expf(-xp1)));
        __stcs(ob + N + n0 + 1, __fdividef(1.0f, 1.0f + __expf(-xg1)));
    }
}

extern "C" void kernel_launch(void* const* d_in, const int* in_sizes, int n_in,
                              void* d_out, int out_size)
{
    const float* user_emb   = (const float*)d_in[0];
    const float* pos_emb    = (const float*)d_in[1];
    const float* neg_emb    = (const float*)d_in[2];
    const float* beh_emb    = (const float*)d_in[3];
    const float* prompt_emb = (const float*)d_in[4];
    float* out = (float*)d_out;

    const int B = in_sizes[3] / DIM;            // 4
    const int N = in_sizes[0] / (B * DIM);      // 131072

    const int total_pairs = (B * N) / 2;
    const int threads = 256;
    const int warps_per_block = threads / 32;
    const int blocks = (total_pairs + warps_per_block - 1) / warps_per_block;

    graph_denoise_kernel<<<blocks, threads>>>(user_emb, pos_emb, neg_emb,
                                              beh_emb, prompt_emb, out, N, B);
}